// round 16
// baseline (speedup 1.0000x reference)
#include <cuda_runtime.h>
#include <cuda_fp16.h>
#include <stdint.h>
#include <math.h>

// Problem constants
#define BATCH 2
#define SEQ   2048
#define DMODEL 768
#define NHEAD 12
#define HD    64
#define KQV_COLS 2304
#define MROWS (BATCH * SEQ)     // 4096

typedef unsigned long long ull;

// ---------------- warp-MMA / async helpers (baseline PTX, sm_103-safe) ------
__device__ __forceinline__ uint32_t smem_u32(const void* p) {
    uint32_t a;
    asm("{ .reg .u64 t; cvta.to.shared.u64 t, %1; cvt.u32.u64 %0, t; }" : "=r"(a) : "l"(p));
    return a;
}
__device__ __forceinline__ void ldsm4(uint32_t* r, uint32_t addr) {
    asm volatile("ldmatrix.sync.aligned.m8n8.x4.shared.b16 {%0,%1,%2,%3}, [%4];"
                 : "=r"(r[0]), "=r"(r[1]), "=r"(r[2]), "=r"(r[3]) : "r"(addr));
}
__device__ __forceinline__ void ldsm4t(uint32_t* r, uint32_t addr) {
    asm volatile("ldmatrix.sync.aligned.m8n8.x4.trans.shared.b16 {%0,%1,%2,%3}, [%4];"
                 : "=r"(r[0]), "=r"(r[1]), "=r"(r[2]), "=r"(r[3]) : "r"(addr));
}
__device__ __forceinline__ void mma16816(float* c, const uint32_t* a, const uint32_t* b) {
    asm volatile("mma.sync.aligned.m16n8k16.row.col.f32.f16.f16.f32 "
                 "{%0,%1,%2,%3}, {%4,%5,%6,%7}, {%8,%9}, {%0,%1,%2,%3};"
                 : "+f"(c[0]), "+f"(c[1]), "+f"(c[2]), "+f"(c[3])
                 : "r"(a[0]), "r"(a[1]), "r"(a[2]), "r"(a[3]), "r"(b[0]), "r"(b[1]));
}
__device__ __forceinline__ void cp16(uint32_t dst, const void* src) {
    asm volatile("cp.async.cg.shared.global [%0], [%1], 16;" :: "r"(dst), "l"(src));
}
__device__ __forceinline__ void cp_commit() { asm volatile("cp.async.commit_group;" ::: "memory"); }
__device__ __forceinline__ void cp_wait0()  { asm volatile("cp.async.wait_group 0;"  ::: "memory"); }
__device__ __forceinline__ float ex2(float x) {
    float r; asm("ex2.approx.f32 %0, %1;" : "=f"(r) : "f"(x)); return r;
}
__device__ __forceinline__ uint32_t packh2(float a, float b) {
    __half2 h = __floats2half2_rn(a, b);
    return *(uint32_t*)&h;
}
__device__ __forceinline__ ull pack2(float lo, float hi) {
    ull r; asm("mov.b64 %0, {%1, %2};" : "=l"(r) : "f"(lo), "f"(hi)); return r;
}
__device__ __forceinline__ ull add2(ull a, ull b) {
    ull d; asm("add.rn.f32x2 %0, %1, %2;" : "=l"(d) : "l"(a), "l"(b)); return d;
}
__device__ __forceinline__ void unpack2(ull v, float& lo, float& hi) {
    asm("mov.b64 {%0, %1}, %2;" : "=f"(lo), "=f"(hi) : "l"(v));
}

// ---------------- scratch (device globals; no allocation allowed) -----------
__device__ __half g_kqv[(size_t)MROWS * KQV_COLS];
__device__ __half g_x16[(size_t)MROWS * DMODEL];
__device__ __half g_wk16[(size_t)KQV_COLS * DMODEL];
__device__ __half g_wp16[(size_t)DMODEL * DMODEL];
__device__ __half g_sa16[(size_t)MROWS * DMODEL];
__device__ float g_part[(size_t)3 * MROWS * DMODEL];    // gemm2 split-K3 partials
__device__ float g_opart[240][128][64];                 // attn split-KV O partials
__device__ float g_l[240][128];                         // attn split-KV l
__device__ int   g_flag[128];
__device__ unsigned short g_tasks[504];
__device__ int g_tc = 0;

#define SCL 0.18033688011112042f          // 0.125 * log2(e)
#define NTASKS 504
#define ATTN_GRID 296

// ---------------- fused fp32->fp16 convert + task table + counter reset -----
__global__ __launch_bounds__(256) void cvt3_kernel(
    const float* __restrict__ a0, __half* __restrict__ o0, int n0,
    const float* __restrict__ a1, __half* __restrict__ o1, int n1,
    const float* __restrict__ a2, __half* __restrict__ o2, int n2)
{
    if (blockIdx.x == 0) {
        int t = threadIdx.x;
        if (t < 128) g_flag[t] = 0;
        if (t == 0) {
            g_tc = 0;
            int idx = 0;
            auto emitFull = [&](int qt) {
                for (int bh = 0; bh < 24; bh++)
                    g_tasks[idx++] = (unsigned short)(qt | (bh << 4) | (2 << 9));
            };
            auto emitHalves = [&](int qt) {
                for (int bh = 0; bh < 24; bh++) {
                    g_tasks[idx++] = (unsigned short)(qt | (bh << 4) | (0 << 9));
                    g_tasks[idx++] = (unsigned short)(qt | (bh << 4) | (1 << 9));
                }
            };
            emitFull(10);
            emitFull(9);
            emitFull(8);
            emitHalves(15); emitFull(7);
            emitHalves(14);
            emitHalves(13); emitFull(6);
            emitHalves(12);
            emitHalves(11); emitFull(5);
            emitFull(4); emitFull(3); emitFull(2); emitFull(1); emitFull(0);
        }
    }

    int i = blockIdx.x * blockDim.x + threadIdx.x;
    const float* in; __half* out;
    if (i < n0)                { in = a0; out = o0; }
    else if (i < n0 + n1)      { i -= n0; in = a1; out = o1; }
    else if (i < n0 + n1 + n2) { i -= n0 + n1; in = a2; out = o2; }
    else return;
    float4 v = ((const float4*)in)[i];
    uint32_t* op = (uint32_t*)out;
    op[2*i]   = packh2(v.x, v.y);
    op[2*i+1] = packh2(v.z, v.w);
}

// ---------------- gemm2 split-K3 combine: out = p0+p1+p2 + bias --------------
__global__ __launch_bounds__(256) void combine3_kernel(const float* __restrict__ bias,
                                                       float* __restrict__ out, int n4)
{
    int i = blockIdx.x * blockDim.x + threadIdx.x;
    if (i >= n4) return;
    const size_t stride = (size_t)MROWS * DMODEL;
    float4 A = ((const float4*)g_part)[i];
    float4 B = ((const float4*)(g_part + stride))[i];
    float4 C = ((const float4*)(g_part + 2 * stride))[i];
    int col = (i * 4) % DMODEL;
    float4 bb = *(const float4*)(bias + col);
    float4 o;
    o.x = A.x + B.x + C.x + bb.x;
    o.y = A.y + B.y + C.y + bb.y;
    o.z = A.z + B.z + C.z + bb.z;
    o.w = A.w + B.w + C.w + bb.w;
    ((float4*)out)[i] = o;
}

// ---------------------------------------------------------------------------
// Single-pass fp16 warp-MMA GEMM, cp.async 2-stage pipeline, optional split-K.
// ---------------------------------------------------------------------------
#define BKG 32
#define LDSW 40
#define G_TILEB (128 * LDSW * 2)
#define G_STAGEB (2 * G_TILEB)
#define G_SMEM (2 * G_STAGEB)
#define NCHUNK (DMODEL / BKG)

__global__ __launch_bounds__(256, 2) void gemm_f16_mma(
    const __half* __restrict__ A, const __half* __restrict__ B,
    const float* __restrict__ bias,
    __half* __restrict__ C16, float* __restrict__ Cpart,
    int qscale, int M, int N)
{
    extern __shared__ char dsm[];
    const uint32_t sbase = smem_u32(dsm);

    const int K = DMODEL;
    const int tid  = threadIdx.x;
    const int wid  = tid >> 5;
    const int lane = tid & 31;
    const int wm = (wid & 3) * 32;
    const int wn = (wid >> 2) * 64;
    const int bm = blockIdx.y * 128;
    const int bn = blockIdx.x * 128;
    const int grp = lane >> 2;
    const int tig = lane & 3;
    const int cbeg = blockIdx.z * (NCHUNK / gridDim.z);
    const int cend = cbeg + NCHUNK / gridDim.z;

    float acc[2][8][4];
#pragma unroll
    for (int mt = 0; mt < 2; mt++)
#pragma unroll
        for (int nt = 0; nt < 8; nt++)
#pragma unroll
            for (int c = 0; c < 4; c++) acc[mt][nt][c] = 0.f;

    const int a_row = lane & 15;
    const int a_c8  = (lane >> 4) * 8;
    const int b_row = ((lane >> 4) * 8) + (lane & 7);
    const int b_c8  = ((lane >> 3) & 1) * 8;

    auto stage_load = [&](int c, int s) {
        const int k0 = c * BKG;
        const uint32_t sb = sbase + s * G_STAGEB;
#pragma unroll
        for (int it = 0; it < 2; it++) {
            int id  = tid + it * 256;
            int row = id >> 2;
            int c8  = (id & 3) * 8;
            size_t ga = (size_t)(bm + row) * K + k0 + c8;
            size_t gb = (size_t)(bn + row) * K + k0 + c8;
            uint32_t so = sb + (uint32_t)(row * LDSW + c8) * 2;
            cp16(so,            A + ga);
            cp16(so + G_TILEB,  B + gb);
        }
        cp_commit();
    };

    stage_load(cbeg, cbeg & 1);

    for (int c = cbeg; c < cend; c++) {
        cp_wait0();
        __syncthreads();
        if (c + 1 < cend) stage_load(c + 1, (c + 1) & 1);

        const uint32_t sb = sbase + (c & 1) * G_STAGEB;
#pragma unroll
        for (int ks = 0; ks < 2; ks++) {
            const int kk = ks * 16;
            uint32_t aF[2][4];
#pragma unroll
            for (int mt = 0; mt < 2; mt++) {
                uint32_t off = sb + (uint32_t)((wm + mt * 16 + a_row) * LDSW + kk + a_c8) * 2;
                ldsm4(aF[mt], off);
            }
            uint32_t bF[8][2];
#pragma unroll
            for (int np = 0; np < 4; np++) {
                uint32_t off = sb + G_TILEB
                             + (uint32_t)((wn + np * 16 + b_row) * LDSW + kk + b_c8) * 2;
                uint32_t r[4];
                ldsm4(r, off);
                bF[2*np][0] = r[0]; bF[2*np][1] = r[1];
                bF[2*np+1][0] = r[2]; bF[2*np+1][1] = r[3];
            }
#pragma unroll
            for (int mt = 0; mt < 2; mt++)
#pragma unroll
                for (int nt = 0; nt < 8; nt++)
                    mma16816(acc[mt][nt], aF[mt], bF[nt]);
        }
    }

#pragma unroll
    for (int mt = 0; mt < 2; mt++) {
        int row0 = bm + wm + mt * 16 + grp;
#pragma unroll
        for (int nt = 0; nt < 8; nt++) {
            int col = bn + wn + nt * 8 + tig * 2;
            if (Cpart) {
                float* dst = Cpart + (size_t)blockIdx.z * M * N;
                float2 o0 = {acc[mt][nt][0], acc[mt][nt][1]};
                float2 o1 = {acc[mt][nt][2], acc[mt][nt][3]};
                *(float2*)(dst + (size_t)row0 * N + col)       = o0;
                *(float2*)(dst + (size_t)(row0 + 8) * N + col) = o1;
            } else {
                float2 b01 = *(const float2*)(bias + col);
                float v0 = acc[mt][nt][0] + b01.x;
                float v1 = acc[mt][nt][1] + b01.y;
                float v2 = acc[mt][nt][2] + b01.x;
                float v3 = acc[mt][nt][3] + b01.y;
                if (qscale) {
                    int cm = col % 192;
                    float qs = (cm >= 64 && cm < 128) ? SCL : 1.0f;
                    v0 *= qs; v1 *= qs; v2 *= qs; v3 *= qs;
                }
                *(uint32_t*)&C16[(size_t)row0 * N + col]       = packh2(v0, v1);
                *(uint32_t*)&C16[(size_t)(row0 + 8) * N + col] = packh2(v2, v3);
            }
        }
    }
}

// ---------------------------------------------------------------------------
// Flash attention: persistent LPT work-queue + split-KV, fp16 mma,
// fixed-shift exp2 softmax. 128-key macro-steps: one cp.async group and ONE
// barrier per 128 keys; two 64-key sub-tiles computed back-to-back.
// ---------------------------------------------------------------------------
#define ALD 72
#define A_SUBT (64 * ALD * 2)             // 9216 B per 64-row sub-tile
#define A_TILEB (128 * ALD * 2)           // 18432 B per array (K or V, 128 rows)
#define A_STAGEB (2 * A_TILEB)            // 36864 B (K + V)
#define A_QOFF (2 * A_STAGEB)             // 73728
#define A_QTILEB (128 * ALD * 2)          // 18432 B
#define A_SMEM (A_QOFF + A_QTILEB)        // 92160 B
#define NEG_BIG (-1.0e30f)

__global__ __launch_bounds__(256, 2) void attn_mma(
    const __half* __restrict__ kqv,
    __half* __restrict__ sa16)
{
    extern __shared__ char dsm[];
    const uint32_t sbase = smem_u32(dsm);
    __half* smh = (__half*)dsm;
    __shared__ int s_task;
    __shared__ int s_flag;

    const int tid  = threadIdx.x;
    const int wid  = tid >> 5;
    const int lane = tid & 31;
    const int grp = lane >> 2;
    const int tig = lane & 3;
    const int a_row = lane & 15;
    const int a_c8  = (lane >> 4) * 8;
    const int b_row = ((lane >> 4) * 8) + (lane & 7);
    const int b_c8  = ((lane >> 3) & 1) * 8;

    while (true) {
        __syncthreads();
        if (tid == 0) s_task = atomicAdd(&g_tc, 1);
        __syncthreads();
        const int ti = s_task;
        if (ti >= NTASKS) break;
        const int task = g_tasks[ti];

        const int qt   = task & 15;
        const int bh   = (task >> 4) & 31;
        const int half = (task >> 9) & 3;
        const int b  = bh / 12;
        const int h  = bh % 12;
        const size_t rowbase = (size_t)b * SEQ;
        const int hoff = h * 192;
        const int row_q0 = qt * 128 + wid * 16 + grp;
        const int row_q1 = row_q0 + 8;
        // macro steps (128 keys each)
        const int mtot = qt + 1;
        const int mid  = (qt + 2) >> 1;
        const int mlo = (half == 1) ? mid : 0;
        const int mhi = (half == 0) ? mid : mtot;

        auto stage_load = [&](int ms, int s) {
            const int key0 = ms * 128;
            const uint32_t sb = sbase + s * A_STAGEB;
#pragma unroll
            for (int i = 0; i < 4; i++) {
                int id = tid + i * 256;
                int row = id >> 3, c8 = (id & 7) * 8;
                size_t g = (rowbase + key0 + row) * KQV_COLS + hoff + c8;
                uint32_t so = sb + (uint32_t)(row * ALD + c8) * 2;
                cp16(so,            kqv + g);          // K
                cp16(so + A_TILEB,  kqv + g + 128);    // V
            }
            cp_commit();
        };

        stage_load(mlo, mlo & 1);

        // stage Q (pre-scaled by SCL in gemm1), hoist fragments to regs
        for (int i = tid; i < 1024; i += 256) {
            int row = i >> 3, c8 = (i & 7) * 8;
            size_t g = (rowbase + qt * 128 + row) * KQV_COLS + hoff + 64 + c8;
            *(uint4*)&smh[(A_QOFF / 2) + row * ALD + c8] = *(const uint4*)&kqv[g];
        }
        __syncthreads();
        uint32_t qF[4][4];
#pragma unroll
        for (int kt = 0; kt < 4; kt++) {
            uint32_t qoff = sbase + A_QOFF
                          + (uint32_t)((wid * 16 + a_row) * ALD + kt * 16 + a_c8) * 2;
            ldsm4(qF[kt], qoff);
        }

        float o[8][4];
#pragma unroll
        for (int nt = 0; nt < 8; nt++)
#pragma unroll
            for (int c = 0; c < 4; c++) o[nt][c] = 0.f;
        float l0 = 0.f, l1 = 0.f;

        for (int ms = mlo; ms < mhi; ms++) {
            cp_wait0();
            __syncthreads();
            if (ms + 1 < mhi) stage_load(ms + 1, (ms + 1) & 1);
            const uint32_t sb = sbase + (ms & 1) * A_STAGEB;

#pragma unroll
            for (int j = 0; j < 2; j++) {
                const int key0 = ms * 128 + j * 64;
                const uint32_t kb = sb + j * A_SUBT;
                const uint32_t vb = sb + A_TILEB + j * A_SUBT;

                // ---- S = Q K^T (exp2 domain; Q pre-scaled), fp16 ----
                float s[8][4];
#pragma unroll
                for (int nt = 0; nt < 8; nt++)
#pragma unroll
                    for (int c = 0; c < 4; c++) s[nt][c] = 0.f;

#pragma unroll
                for (int kt = 0; kt < 4; kt++) {
                    uint32_t bF[8][2];
#pragma unroll
                    for (int np = 0; np < 4; np++) {
                        uint32_t r[4];
                        uint32_t off = kb + (uint32_t)((np * 16 + b_row) * ALD + kt * 16 + b_c8) * 2;
                        ldsm4(r, off);
                        bF[2*np][0] = r[0]; bF[2*np][1] = r[1];
                        bF[2*np+1][0] = r[2]; bF[2*np+1][1] = r[3];
                    }
#pragma unroll
                    for (int nt = 0; nt < 8; nt++) mma16816(s[nt], qF[kt], bF[nt]);
                }

                // causal mask (diagonal-straddling sub-steps only)
                if (key0 + 64 > qt * 128) {
#pragma unroll
                    for (int nt = 0; nt < 8; nt++) {
                        int colbase = key0 + nt * 8 + tig * 2;
                        if (colbase     > row_q0) s[nt][0] = NEG_BIG;
                        if (colbase + 1 > row_q0) s[nt][1] = NEG_BIG;
                        if (colbase     > row_q1) s[nt][2] = NEG_BIG;
                        if (colbase + 1 > row_q1) s[nt][3] = NEG_BIG;
                    }
                }

                // fixed-shift exp2 + packed pair-sum
                ull psA = 0ull;
#pragma unroll
                for (int nt = 0; nt < 8; nt++) {
                    s[nt][0] = ex2(s[nt][0]);
                    s[nt][1] = ex2(s[nt][1]);
                    s[nt][2] = ex2(s[nt][2]);
                    s[nt][3] = ex2(s[nt][3]);
                    psA = add2(psA, pack2(s[nt][0], s[nt][2]));
                    psA = add2(psA, pack2(s[nt][1], s[nt][3]));
                }
                float ps0, ps1;
                unpack2(psA, ps0, ps1);
                l0 += ps0;
                l1 += ps1;

                // P fragments
                uint32_t aP[4][4];
#pragma unroll
                for (int kt = 0; kt < 4; kt++) {
                    aP[kt][0] = packh2(s[2*kt][0],   s[2*kt][1]);
                    aP[kt][1] = packh2(s[2*kt][2],   s[2*kt][3]);
                    aP[kt][2] = packh2(s[2*kt+1][0], s[2*kt+1][1]);
                    aP[kt][3] = packh2(s[2*kt+1][2], s[2*kt+1][3]);
                }

                // O += P V
#pragma unroll
                for (int kt = 0; kt < 4; kt++) {
                    uint32_t bvF[8][2];
#pragma unroll
                    for (int np2 = 0; np2 < 4; np2++) {
                        uint32_t r[4];
                        uint32_t off = vb + (uint32_t)((kt * 16 + a_row) * ALD + np2 * 16 + a_c8) * 2;
                        ldsm4t(r, off);
                        bvF[2*np2][0] = r[0]; bvF[2*np2][1] = r[1];
                        bvF[2*np2+1][0] = r[2]; bvF[2*np2+1][1] = r[3];
                    }
#pragma unroll
                    for (int nt2 = 0; nt2 < 8; nt2++) mma16816(o[nt2], aP[kt], bvF[nt2]);
                }
            }
        }

        // finish lane-group reduction of l
        l0 += __shfl_xor_sync(0xFFFFFFFFu, l0, 1);
        l0 += __shfl_xor_sync(0xFFFFFFFFu, l0, 2);
        l1 += __shfl_xor_sync(0xFFFFFFFFu, l1, 1);
        l1 += __shfl_xor_sync(0xFFFFFFFFu, l1, 2);

        if (half == 2) {
            float inv0 = 1.0f / l0, inv1 = 1.0f / l1;
            size_t r0 = (rowbase + qt * 128 + wid * 16 + grp) * DMODEL;
            size_t r1 = r0 + (size_t)8 * DMODEL;
#pragma unroll
            for (int nt2 = 0; nt2 < 8; nt2++) {
                int col = h * HD + nt2 * 8 + tig * 2;
                *(uint32_t*)&sa16[r0 + col] = packh2(o[nt2][0] * inv0, o[nt2][1] * inv0);
                *(uint32_t*)&sa16[r1 + col] = packh2(o[nt2][2] * inv1, o[nt2][3] * inv1);
            }
        } else {
            // split-KV: store partial (O, l); second finisher merges
            const int tile = (qt - 11) * 24 + bh;
            const int sub  = tile * 2 + half;
            const int lr0 = wid * 16 + grp, lr1 = lr0 + 8;
#pragma unroll
            for (int nt2 = 0; nt2 < 8; nt2++) {
                int col = nt2 * 8 + tig * 2;
                *(float2*)&g_opart[sub][lr0][col] = make_float2(o[nt2][0], o[nt2][1]);
                *(float2*)&g_opart[sub][lr1][col] = make_float2(o[nt2][2], o[nt2][3]);
            }
            if (tig == 0) {
                g_l[sub][lr0] = l0;
                g_l[sub][lr1] = l1;
            }
            __threadfence();
            __syncthreads();
            if (tid == 0) s_flag = atomicAdd(&g_flag[tile], 1);
            __syncthreads();
            if (s_flag == 1) {
                __threadfence();
                if (tid < 128) {
                    const int row = tid;
                    const int sA = tile * 2, sB = sA + 1;
                    float inv = 1.0f / (g_l[sA][row] + g_l[sB][row]);
                    size_t gr = (rowbase + qt * 128 + row) * DMODEL + h * HD;
#pragma unroll
                    for (int c4 = 0; c4 < 16; c4++) {
                        float4 A = *(float4*)&g_opart[sA][row][c4 * 4];
                        float4 B = *(float4*)&g_opart[sB][row][c4 * 4];
                        float v0 = (A.x + B.x) * inv;
                        float v1 = (A.y + B.y) * inv;
                        float v2 = (A.z + B.z) * inv;
                        float v3 = (A.w + B.w) * inv;
                        *(uint32_t*)&sa16[gr + c4*4]     = packh2(v0, v1);
                        *(uint32_t*)&sa16[gr + c4*4 + 2] = packh2(v2, v3);
                    }
                }
            }
        }
    }
}

// ---------------------------------------------------------------------------
extern "C" void kernel_launch(void* const* d_in, const int* in_sizes, int n_in,
                              void* d_out, int out_size)
{
    const float* x     = (const float*)d_in[0];
    const float* Wkqv  = (const float*)d_in[1];
    const float* bkqv  = (const float*)d_in[2];
    const float* Wproj = (const float*)d_in[3];
    const float* bproj = (const float*)d_in[4];
    float* out = (float*)d_out;

    __half *kqv, *x16, *wk16, *wp16, *sa16;
    float* part;
    cudaGetSymbolAddress((void**)&kqv,  g_kqv);
    cudaGetSymbolAddress((void**)&x16,  g_x16);
    cudaGetSymbolAddress((void**)&wk16, g_wk16);
    cudaGetSymbolAddress((void**)&wp16, g_wp16);
    cudaGetSymbolAddress((void**)&sa16, g_sa16);
    cudaGetSymbolAddress((void**)&part, g_part);

    static bool attrs_set = false;
    if (!attrs_set) {
        cudaFuncSetAttribute(gemm_f16_mma,
                             cudaFuncAttributeMaxDynamicSharedMemorySize, G_SMEM);
        cudaFuncSetAttribute(attn_mma,
                             cudaFuncAttributeMaxDynamicSharedMemorySize, A_SMEM);
        attrs_set = true;
    }

    // fused converts + task table + counter reset
    {
        int n0 = MROWS * DMODEL / 4;
        int n1 = KQV_COLS * DMODEL / 4;
        int n2 = DMODEL * DMODEL / 4;
        int total = n0 + n1 + n2;
        cvt3_kernel<<<(total + 255) / 256, 256>>>(x, x16, n0,
                                                  Wkqv, wk16, n1,
                                                  Wproj, wp16, n2);
    }
    // GEMM1: kqv(fp16) = x @ Wkqv^T + bkqv (Q columns pre-scaled by SCL)
    {
        dim3 grid(KQV_COLS / 128, MROWS / 128, 1);
        gemm_f16_mma<<<grid, 256, G_SMEM>>>(x16, wk16, bkqv,
                                            kqv, nullptr, 1, MROWS, KQV_COLS);
    }
    // attention (persistent work-queue, split-KV for long tasks)
    {
        attn_mma<<<ATTN_GRID, 256, A_SMEM>>>(kqv, sa16);
    }
    // GEMM2 split-K3: partials, then combine with bias
    {
        dim3 grid(DMODEL / 128, MROWS / 128, 3);
        gemm_f16_mma<<<grid, 256, G_SMEM>>>(sa16, wp16, nullptr,
                                            nullptr, part, 0, MROWS, DMODEL);
        int n4 = MROWS * DMODEL / 4;
        combine3_kernel<<<(n4 + 255) / 256, 256>>>(bproj, out, n4);
    }
}

// round 17
// speedup vs baseline: 1.0151x; 1.0151x over previous
#include <cuda_runtime.h>
#include <cuda_fp16.h>
#include <stdint.h>
#include <math.h>

// Problem constants
#define BATCH 2
#define SEQ   2048
#define DMODEL 768
#define NHEAD 12
#define HD    64
#define KQV_COLS 2304
#define MROWS (BATCH * SEQ)     // 4096

typedef unsigned long long ull;

// ---------------- warp-MMA / async helpers (baseline PTX, sm_103-safe) ------
__device__ __forceinline__ uint32_t smem_u32(const void* p) {
    uint32_t a;
    asm("{ .reg .u64 t; cvta.to.shared.u64 t, %1; cvt.u32.u64 %0, t; }" : "=r"(a) : "l"(p));
    return a;
}
__device__ __forceinline__ void ldsm4(uint32_t* r, uint32_t addr) {
    asm volatile("ldmatrix.sync.aligned.m8n8.x4.shared.b16 {%0,%1,%2,%3}, [%4];"
                 : "=r"(r[0]), "=r"(r[1]), "=r"(r[2]), "=r"(r[3]) : "r"(addr));
}
__device__ __forceinline__ void ldsm4t(uint32_t* r, uint32_t addr) {
    asm volatile("ldmatrix.sync.aligned.m8n8.x4.trans.shared.b16 {%0,%1,%2,%3}, [%4];"
                 : "=r"(r[0]), "=r"(r[1]), "=r"(r[2]), "=r"(r[3]) : "r"(addr));
}
__device__ __forceinline__ void mma16816(float* c, const uint32_t* a, const uint32_t* b) {
    asm volatile("mma.sync.aligned.m16n8k16.row.col.f32.f16.f16.f32 "
                 "{%0,%1,%2,%3}, {%4,%5,%6,%7}, {%8,%9}, {%0,%1,%2,%3};"
                 : "+f"(c[0]), "+f"(c[1]), "+f"(c[2]), "+f"(c[3])
                 : "r"(a[0]), "r"(a[1]), "r"(a[2]), "r"(a[3]), "r"(b[0]), "r"(b[1]));
}
__device__ __forceinline__ void cp16(uint32_t dst, const void* src) {
    asm volatile("cp.async.cg.shared.global [%0], [%1], 16;" :: "r"(dst), "l"(src));
}
__device__ __forceinline__ void cp_commit() { asm volatile("cp.async.commit_group;" ::: "memory"); }
__device__ __forceinline__ void cp_wait0()  { asm volatile("cp.async.wait_group 0;"  ::: "memory"); }
__device__ __forceinline__ float ex2(float x) {
    float r; asm("ex2.approx.f32 %0, %1;" : "=f"(r) : "f"(x)); return r;
}
__device__ __forceinline__ uint32_t packh2(float a, float b) {
    __half2 h = __floats2half2_rn(a, b);
    return *(uint32_t*)&h;
}
__device__ __forceinline__ ull pack2(float lo, float hi) {
    ull r; asm("mov.b64 %0, {%1, %2};" : "=l"(r) : "f"(lo), "f"(hi)); return r;
}
__device__ __forceinline__ ull add2(ull a, ull b) {
    ull d; asm("add.rn.f32x2 %0, %1, %2;" : "=l"(d) : "l"(a), "l"(b)); return d;
}
__device__ __forceinline__ void unpack2(ull v, float& lo, float& hi) {
    asm("mov.b64 {%0, %1}, %2;" : "=f"(lo), "=f"(hi) : "l"(v));
}

// ---------------- scratch (device globals; no allocation allowed) -----------
__device__ __half g_kqv[(size_t)MROWS * KQV_COLS];
__device__ __half g_x16[(size_t)MROWS * DMODEL];
__device__ __half g_wk16[(size_t)KQV_COLS * DMODEL];
__device__ __half g_wp16[(size_t)DMODEL * DMODEL];
__device__ __half g_sa16[(size_t)MROWS * DMODEL];
__device__ float g_part[(size_t)3 * MROWS * DMODEL];    // gemm2 split-K3 partials
__device__ float g_opart[240][128][64];                 // attn split-KV O partials
__device__ float g_l[240][128];                         // attn split-KV l
__device__ int   g_flag[128];                           // attn split-tile finish count
__device__ int   g_flag2[192];                          // gemm2 split-K finish count
__device__ unsigned short g_tasks[504];
__device__ int g_tc = 0;

#define SCL 0.18033688011112042f          // 0.125 * log2(e)
#define NTASKS 504
#define ATTN_GRID 296

// ---------------- fused fp32->fp16 convert + task table + counter reset -----
__global__ __launch_bounds__(256) void cvt3_kernel(
    const float* __restrict__ a0, __half* __restrict__ o0, int n0,
    const float* __restrict__ a1, __half* __restrict__ o1, int n1,
    const float* __restrict__ a2, __half* __restrict__ o2, int n2)
{
    if (blockIdx.x == 0) {
        int t = threadIdx.x;
        if (t < 128) g_flag[t] = 0;
        if (t < 192) g_flag2[t] = 0;
        if (t == 0) {
            g_tc = 0;
            int idx = 0;
            auto emitFull = [&](int qt) {
                for (int bh = 0; bh < 24; bh++)
                    g_tasks[idx++] = (unsigned short)(qt | (bh << 4) | (2 << 9));
            };
            auto emitHalves = [&](int qt) {
                for (int bh = 0; bh < 24; bh++) {
                    g_tasks[idx++] = (unsigned short)(qt | (bh << 4) | (0 << 9));
                    g_tasks[idx++] = (unsigned short)(qt | (bh << 4) | (1 << 9));
                }
            };
            emitFull(10);
            emitFull(9);
            emitFull(8);
            emitHalves(15); emitFull(7);
            emitHalves(14);
            emitHalves(13); emitFull(6);
            emitHalves(12);
            emitHalves(11); emitFull(5);
            emitFull(4); emitFull(3); emitFull(2); emitFull(1); emitFull(0);
        }
    }

    int i = blockIdx.x * blockDim.x + threadIdx.x;
    const float* in; __half* out;
    if (i < n0)                { in = a0; out = o0; }
    else if (i < n0 + n1)      { i -= n0; in = a1; out = o1; }
    else if (i < n0 + n1 + n2) { i -= n0 + n1; in = a2; out = o2; }
    else return;
    float4 v = ((const float4*)in)[i];
    uint32_t* op = (uint32_t*)out;
    op[2*i]   = packh2(v.x, v.y);
    op[2*i+1] = packh2(v.z, v.w);
}

// ---------------------------------------------------------------------------
// Single-pass fp16 warp-MMA GEMM, cp.async 2-stage pipeline, optional split-K.
// Split-K mode (Cpart != null): each z writes its partial; the LAST finisher
// of each output tile combines p0+p1+p2+bias inline (fixed z order) -> Cout.
// ---------------------------------------------------------------------------
#define BKG 32
#define LDSW 40
#define G_TILEB (128 * LDSW * 2)
#define G_STAGEB (2 * G_TILEB)
#define G_SMEM (2 * G_STAGEB)
#define NCHUNK (DMODEL / BKG)

__global__ __launch_bounds__(256, 2) void gemm_f16_mma(
    const __half* __restrict__ A, const __half* __restrict__ B,
    const float* __restrict__ bias,
    __half* __restrict__ C16, float* __restrict__ Cpart,
    float* __restrict__ Cout,
    int qscale, int M, int N)
{
    extern __shared__ char dsm[];
    const uint32_t sbase = smem_u32(dsm);

    const int K = DMODEL;
    const int tid  = threadIdx.x;
    const int wid  = tid >> 5;
    const int lane = tid & 31;
    const int wm = (wid & 3) * 32;
    const int wn = (wid >> 2) * 64;
    const int bm = blockIdx.y * 128;
    const int bn = blockIdx.x * 128;
    const int grp = lane >> 2;
    const int tig = lane & 3;
    const int cbeg = blockIdx.z * (NCHUNK / gridDim.z);
    const int cend = cbeg + NCHUNK / gridDim.z;

    float acc[2][8][4];
#pragma unroll
    for (int mt = 0; mt < 2; mt++)
#pragma unroll
        for (int nt = 0; nt < 8; nt++)
#pragma unroll
            for (int c = 0; c < 4; c++) acc[mt][nt][c] = 0.f;

    const int a_row = lane & 15;
    const int a_c8  = (lane >> 4) * 8;
    const int b_row = ((lane >> 4) * 8) + (lane & 7);
    const int b_c8  = ((lane >> 3) & 1) * 8;

    auto stage_load = [&](int c, int s) {
        const int k0 = c * BKG;
        const uint32_t sb = sbase + s * G_STAGEB;
#pragma unroll
        for (int it = 0; it < 2; it++) {
            int id  = tid + it * 256;
            int row = id >> 2;
            int c8  = (id & 3) * 8;
            size_t ga = (size_t)(bm + row) * K + k0 + c8;
            size_t gb = (size_t)(bn + row) * K + k0 + c8;
            uint32_t so = sb + (uint32_t)(row * LDSW + c8) * 2;
            cp16(so,            A + ga);
            cp16(so + G_TILEB,  B + gb);
        }
        cp_commit();
    };

    stage_load(cbeg, cbeg & 1);

    for (int c = cbeg; c < cend; c++) {
        cp_wait0();
        __syncthreads();
        if (c + 1 < cend) stage_load(c + 1, (c + 1) & 1);

        const uint32_t sb = sbase + (c & 1) * G_STAGEB;
#pragma unroll
        for (int ks = 0; ks < 2; ks++) {
            const int kk = ks * 16;
            uint32_t aF[2][4];
#pragma unroll
            for (int mt = 0; mt < 2; mt++) {
                uint32_t off = sb + (uint32_t)((wm + mt * 16 + a_row) * LDSW + kk + a_c8) * 2;
                ldsm4(aF[mt], off);
            }
            uint32_t bF[8][2];
#pragma unroll
            for (int np = 0; np < 4; np++) {
                uint32_t off = sb + G_TILEB
                             + (uint32_t)((wn + np * 16 + b_row) * LDSW + kk + b_c8) * 2;
                uint32_t r[4];
                ldsm4(r, off);
                bF[2*np][0] = r[0]; bF[2*np][1] = r[1];
                bF[2*np+1][0] = r[2]; bF[2*np+1][1] = r[3];
            }
#pragma unroll
            for (int mt = 0; mt < 2; mt++)
#pragma unroll
                for (int nt = 0; nt < 8; nt++)
                    mma16816(acc[mt][nt], aF[mt], bF[nt]);
        }
    }

    if (Cpart) {
        // write this z-slice's partial
        float* dst = Cpart + (size_t)blockIdx.z * M * N;
#pragma unroll
        for (int mt = 0; mt < 2; mt++) {
            int row0 = bm + wm + mt * 16 + grp;
#pragma unroll
            for (int nt = 0; nt < 8; nt++) {
                int col = bn + wn + nt * 8 + tig * 2;
                float2 o0 = {acc[mt][nt][0], acc[mt][nt][1]};
                float2 o1 = {acc[mt][nt][2], acc[mt][nt][3]};
                *(float2*)(dst + (size_t)row0 * N + col)       = o0;
                *(float2*)(dst + (size_t)(row0 + 8) * N + col) = o1;
            }
        }
        // last finisher of this xy tile combines (fixed z order: (p0+p1)+p2+bias)
        __threadfence();
        __shared__ int sf;
        __syncthreads();
        if (tid == 0) sf = atomicAdd(&g_flag2[blockIdx.y * gridDim.x + blockIdx.x], 1);
        __syncthreads();
        if (sf == 2) {
            __threadfence();
            const size_t stride = (size_t)M * N;
#pragma unroll
            for (int it = 0; it < 16; it++) {
                int idx = tid + it * 256;          // 4096 float4 in tile
                int row = idx >> 5;                // 32 float4 per 128-col row
                int c4  = (idx & 31) * 4;
                size_t off = (size_t)(bm + row) * N + bn + c4;
                float4 A4 = *(const float4*)(Cpart + off);
                float4 B4 = *(const float4*)(Cpart + stride + off);
                float4 C4 = *(const float4*)(Cpart + 2 * stride + off);
                float4 bb = *(const float4*)(bias + bn + c4);
                float4 o;
                o.x = A4.x + B4.x + C4.x + bb.x;
                o.y = A4.y + B4.y + C4.y + bb.y;
                o.z = A4.z + B4.z + C4.z + bb.z;
                o.w = A4.w + B4.w + C4.w + bb.w;
                *(float4*)(Cout + off) = o;
            }
        }
    } else {
#pragma unroll
        for (int mt = 0; mt < 2; mt++) {
            int row0 = bm + wm + mt * 16 + grp;
#pragma unroll
            for (int nt = 0; nt < 8; nt++) {
                int col = bn + wn + nt * 8 + tig * 2;
                float2 b01 = *(const float2*)(bias + col);
                float v0 = acc[mt][nt][0] + b01.x;
                float v1 = acc[mt][nt][1] + b01.y;
                float v2 = acc[mt][nt][2] + b01.x;
                float v3 = acc[mt][nt][3] + b01.y;
                if (qscale) {
                    int cm = col % 192;
                    float qs = (cm >= 64 && cm < 128) ? SCL : 1.0f;
                    v0 *= qs; v1 *= qs; v2 *= qs; v3 *= qs;
                }
                *(uint32_t*)&C16[(size_t)row0 * N + col]       = packh2(v0, v1);
                *(uint32_t*)&C16[(size_t)(row0 + 8) * N + col] = packh2(v2, v3);
            }
        }
    }
}

// ---------------------------------------------------------------------------
// Flash attention: persistent LPT work-queue + split-KV, fp16 mma,
// fixed-shift exp2 softmax, 64-key steps (round-15 structure).
// ---------------------------------------------------------------------------
#define ALD 72
#define A_TILEB (64 * ALD * 2)            // 9216 B
#define A_STAGEB (2 * A_TILEB)            // 18432 B (K + V)
#define A_QOFF (2 * A_STAGEB)             // 36864
#define A_QTILEB (128 * ALD * 2)          // 18432 B
#define A_SMEM (A_QOFF + A_QTILEB)        // 55296 B
#define NEG_BIG (-1.0e30f)

__global__ __launch_bounds__(256, 2) void attn_mma(
    const __half* __restrict__ kqv,
    __half* __restrict__ sa16)
{
    extern __shared__ char dsm[];
    const uint32_t sbase = smem_u32(dsm);
    __half* smh = (__half*)dsm;
    __shared__ int s_task;
    __shared__ int s_flag;

    const int tid  = threadIdx.x;
    const int wid  = tid >> 5;
    const int lane = tid & 31;
    const int grp = lane >> 2;
    const int tig = lane & 3;
    const int a_row = lane & 15;
    const int a_c8  = (lane >> 4) * 8;
    const int b_row = ((lane >> 4) * 8) + (lane & 7);
    const int b_c8  = ((lane >> 3) & 1) * 8;

    while (true) {
        __syncthreads();
        if (tid == 0) s_task = atomicAdd(&g_tc, 1);
        __syncthreads();
        const int ti = s_task;
        if (ti >= NTASKS) break;
        const int task = g_tasks[ti];

        const int qt   = task & 15;
        const int bh   = (task >> 4) & 31;
        const int half = (task >> 9) & 3;
        const int b  = bh / 12;
        const int h  = bh % 12;
        const size_t rowbase = (size_t)b * SEQ;
        const int hoff = h * 192;
        const int row_q0 = qt * 128 + wid * 16 + grp;
        const int row_q1 = row_q0 + 8;
        const int nsteps = 2 * qt + 2;
        const int step_lo = (half == 1) ? (qt + 1) : 0;
        const int step_hi = (half == 0) ? (qt + 1) : nsteps;

        auto stage_load = [&](int step, int s) {
            const int key0 = step * 64;
            const uint32_t sb = sbase + s * A_STAGEB;
#pragma unroll
            for (int i = 0; i < 2; i++) {
                int id = tid + i * 256;
                int row = id >> 3, c8 = (id & 7) * 8;
                size_t g = (rowbase + key0 + row) * KQV_COLS + hoff + c8;
                uint32_t so = sb + (uint32_t)(row * ALD + c8) * 2;
                cp16(so,            kqv + g);          // K
                cp16(so + A_TILEB,  kqv + g + 128);    // V
            }
            cp_commit();
        };

        stage_load(step_lo, step_lo & 1);

        // stage Q (pre-scaled by SCL in gemm1), hoist fragments to regs
        for (int i = tid; i < 1024; i += 256) {
            int row = i >> 3, c8 = (i & 7) * 8;
            size_t g = (rowbase + qt * 128 + row) * KQV_COLS + hoff + 64 + c8;
            *(uint4*)&smh[(A_QOFF / 2) + row * ALD + c8] = *(const uint4*)&kqv[g];
        }
        __syncthreads();
        uint32_t qF[4][4];
#pragma unroll
        for (int kt = 0; kt < 4; kt++) {
            uint32_t qoff = sbase + A_QOFF
                          + (uint32_t)((wid * 16 + a_row) * ALD + kt * 16 + a_c8) * 2;
            ldsm4(qF[kt], qoff);
        }

        float o[8][4];
#pragma unroll
        for (int nt = 0; nt < 8; nt++)
#pragma unroll
            for (int c = 0; c < 4; c++) o[nt][c] = 0.f;
        float l0 = 0.f, l1 = 0.f;

        for (int step = step_lo; step < step_hi; step++) {
            const int key0 = step * 64;
            cp_wait0();
            __syncthreads();
            if (step + 1 < step_hi) stage_load(step + 1, (step + 1) & 1);
            const uint32_t sb = sbase + (step & 1) * A_STAGEB;

            // ---- S = Q K^T (exp2 domain; Q pre-scaled), fp16 ----
            float s[8][4];
#pragma unroll
            for (int nt = 0; nt < 8; nt++)
#pragma unroll
                for (int c = 0; c < 4; c++) s[nt][c] = 0.f;

#pragma unroll
            for (int kt = 0; kt < 4; kt++) {
                uint32_t bF[8][2];
#pragma unroll
                for (int np = 0; np < 4; np++) {
                    uint32_t r[4];
                    uint32_t off = sb + (uint32_t)((np * 16 + b_row) * ALD + kt * 16 + b_c8) * 2;
                    ldsm4(r, off);
                    bF[2*np][0] = r[0]; bF[2*np][1] = r[1];
                    bF[2*np+1][0] = r[2]; bF[2*np+1][1] = r[3];
                }
#pragma unroll
                for (int nt = 0; nt < 8; nt++) mma16816(s[nt], qF[kt], bF[nt]);
            }

            // causal mask (diagonal-straddling steps only)
            if (key0 + 64 > qt * 128) {
#pragma unroll
                for (int nt = 0; nt < 8; nt++) {
                    int colbase = key0 + nt * 8 + tig * 2;
                    if (colbase     > row_q0) s[nt][0] = NEG_BIG;
                    if (colbase + 1 > row_q0) s[nt][1] = NEG_BIG;
                    if (colbase     > row_q1) s[nt][2] = NEG_BIG;
                    if (colbase + 1 > row_q1) s[nt][3] = NEG_BIG;
                }
            }

            // fixed-shift exp2 + packed pair-sum
            ull psA = 0ull;
#pragma unroll
            for (int nt = 0; nt < 8; nt++) {
                s[nt][0] = ex2(s[nt][0]);
                s[nt][1] = ex2(s[nt][1]);
                s[nt][2] = ex2(s[nt][2]);
                s[nt][3] = ex2(s[nt][3]);
                psA = add2(psA, pack2(s[nt][0], s[nt][2]));
                psA = add2(psA, pack2(s[nt][1], s[nt][3]));
            }
            float ps0, ps1;
            unpack2(psA, ps0, ps1);
            l0 += ps0;
            l1 += ps1;

            // P fragments
            uint32_t aP[4][4];
#pragma unroll
            for (int kt = 0; kt < 4; kt++) {
                aP[kt][0] = packh2(s[2*kt][0],   s[2*kt][1]);
                aP[kt][1] = packh2(s[2*kt][2],   s[2*kt][3]);
                aP[kt][2] = packh2(s[2*kt+1][0], s[2*kt+1][1]);
                aP[kt][3] = packh2(s[2*kt+1][2], s[2*kt+1][3]);
            }

            // O += P V
#pragma unroll
            for (int kt = 0; kt < 4; kt++) {
                uint32_t bvF[8][2];
#pragma unroll
                for (int np2 = 0; np2 < 4; np2++) {
                    uint32_t r[4];
                    uint32_t off = sb + A_TILEB
                                 + (uint32_t)((kt * 16 + a_row) * ALD + np2 * 16 + a_c8) * 2;
                    ldsm4t(r, off);
                    bvF[2*np2][0] = r[0]; bvF[2*np2][1] = r[1];
                    bvF[2*np2+1][0] = r[2]; bvF[2*np2+1][1] = r[3];
                }
#pragma unroll
                for (int nt2 = 0; nt2 < 8; nt2++) mma16816(o[nt2], aP[kt], bvF[nt2]);
            }
        }

        // finish lane-group reduction of l
        l0 += __shfl_xor_sync(0xFFFFFFFFu, l0, 1);
        l0 += __shfl_xor_sync(0xFFFFFFFFu, l0, 2);
        l1 += __shfl_xor_sync(0xFFFFFFFFu, l1, 1);
        l1 += __shfl_xor_sync(0xFFFFFFFFu, l1, 2);

        if (half == 2) {
            float inv0 = 1.0f / l0, inv1 = 1.0f / l1;
            size_t r0 = (rowbase + qt * 128 + wid * 16 + grp) * DMODEL;
            size_t r1 = r0 + (size_t)8 * DMODEL;
#pragma unroll
            for (int nt2 = 0; nt2 < 8; nt2++) {
                int col = h * HD + nt2 * 8 + tig * 2;
                *(uint32_t*)&sa16[r0 + col] = packh2(o[nt2][0] * inv0, o[nt2][1] * inv0);
                *(uint32_t*)&sa16[r1 + col] = packh2(o[nt2][2] * inv1, o[nt2][3] * inv1);
            }
        } else {
            // split-KV: store partial (O, l); second finisher merges
            const int tile = (qt - 11) * 24 + bh;
            const int sub  = tile * 2 + half;
            const int lr0 = wid * 16 + grp, lr1 = lr0 + 8;
#pragma unroll
            for (int nt2 = 0; nt2 < 8; nt2++) {
                int col = nt2 * 8 + tig * 2;
                *(float2*)&g_opart[sub][lr0][col] = make_float2(o[nt2][0], o[nt2][1]);
                *(float2*)&g_opart[sub][lr1][col] = make_float2(o[nt2][2], o[nt2][3]);
            }
            if (tig == 0) {
                g_l[sub][lr0] = l0;
                g_l[sub][lr1] = l1;
            }
            __threadfence();
            __syncthreads();
            if (tid == 0) s_flag = atomicAdd(&g_flag[tile], 1);
            __syncthreads();
            if (s_flag == 1) {
                __threadfence();
                if (tid < 128) {
                    const int row = tid;
                    const int sA = tile * 2, sB = sA + 1;
                    float inv = 1.0f / (g_l[sA][row] + g_l[sB][row]);
                    size_t gr = (rowbase + qt * 128 + row) * DMODEL + h * HD;
#pragma unroll
                    for (int c4 = 0; c4 < 16; c4++) {
                        float4 A = *(float4*)&g_opart[sA][row][c4 * 4];
                        float4 B = *(float4*)&g_opart[sB][row][c4 * 4];
                        float v0 = (A.x + B.x) * inv;
                        float v1 = (A.y + B.y) * inv;
                        float v2 = (A.z + B.z) * inv;
                        float v3 = (A.w + B.w) * inv;
                        *(uint32_t*)&sa16[gr + c4*4]     = packh2(v0, v1);
                        *(uint32_t*)&sa16[gr + c4*4 + 2] = packh2(v2, v3);
                    }
                }
            }
        }
    }
}

// ---------------------------------------------------------------------------
extern "C" void kernel_launch(void* const* d_in, const int* in_sizes, int n_in,
                              void* d_out, int out_size)
{
    const float* x     = (const float*)d_in[0];
    const float* Wkqv  = (const float*)d_in[1];
    const float* bkqv  = (const float*)d_in[2];
    const float* Wproj = (const float*)d_in[3];
    const float* bproj = (const float*)d_in[4];
    float* out = (float*)d_out;

    __half *kqv, *x16, *wk16, *wp16, *sa16;
    float* part;
    cudaGetSymbolAddress((void**)&kqv,  g_kqv);
    cudaGetSymbolAddress((void**)&x16,  g_x16);
    cudaGetSymbolAddress((void**)&wk16, g_wk16);
    cudaGetSymbolAddress((void**)&wp16, g_wp16);
    cudaGetSymbolAddress((void**)&sa16, g_sa16);
    cudaGetSymbolAddress((void**)&part, g_part);

    static bool attrs_set = false;
    if (!attrs_set) {
        cudaFuncSetAttribute(gemm_f16_mma,
                             cudaFuncAttributeMaxDynamicSharedMemorySize, G_SMEM);
        cudaFuncSetAttribute(attn_mma,
                             cudaFuncAttributeMaxDynamicSharedMemorySize, A_SMEM);
        attrs_set = true;
    }

    // fused converts + task table + counter resets
    {
        int n0 = MROWS * DMODEL / 4;
        int n1 = KQV_COLS * DMODEL / 4;
        int n2 = DMODEL * DMODEL / 4;
        int total = n0 + n1 + n2;
        cvt3_kernel<<<(total + 255) / 256, 256>>>(x, x16, n0,
                                                  Wkqv, wk16, n1,
                                                  Wproj, wp16, n2);
    }
    // GEMM1: kqv(fp16) = x @ Wkqv^T + bkqv (Q columns pre-scaled by SCL)
    {
        dim3 grid(KQV_COLS / 128, MROWS / 128, 1);
        gemm_f16_mma<<<grid, 256, G_SMEM>>>(x16, wk16, bkqv,
                                            kqv, nullptr, nullptr, 1, MROWS, KQV_COLS);
    }
    // attention (persistent work-queue, split-KV for long tasks)
    {
        attn_mma<<<ATTN_GRID, 256, A_SMEM>>>(kqv, sa16);
    }
    // GEMM2 split-K3 with fused in-kernel combine (last finisher writes out)
    {
        dim3 grid(DMODEL / 128, MROWS / 128, 3);
        gemm_f16_mma<<<grid, 256, G_SMEM>>>(sa16, wp16, bproj,
                                            nullptr, part, out, 0, MROWS, DMODEL);
    }
}